// round 2
// baseline (speedup 1.0000x reference)
#include <cuda_runtime.h>
#include <cstdint>
#include <cstddef>

// LSTM: batch B == H == 1024, S = 128, I = 1024.
// Per step: gates[1024 x 4096] = [h | x_s] (1024 x 2048) @ Wcat (2048 x 4096) + bias
// Split-TF32 (3-term) for ~fp32 accuracy on tensor cores.
// Output: h (1M floats) then c (1M floats).

#define HID  1024
#define SLEN 128
#define NGC  4096   // 4 gates * HID  (col order: i, f, g, o)
#define KTOT 2048   // HID (from h) + HID (from x_s)

#define BM 128
#define BN 128
#define BK 16

// Static device scratch (allocation is forbidden)
__device__ float g_Whi[(size_t)KTOT * NGC];    // tf32 high part of weights, 32 MB
__device__ float g_Wlo[(size_t)KTOT * NGC];    // tf32 low (residual) part,  32 MB
__device__ float g_bias[NGC];
__device__ float g_gates[(size_t)HID * NGC];   // pre-activation gates, 16 MB

__device__ __forceinline__ float to_tf32(float x) {
    float r;
    asm("cvt.rna.tf32.f32 %0, %1;" : "=f"(r) : "f"(x));
    return r;
}

// ---------------------------------------------------------------------------
// Prep: split weights into (hi, lo) tf32 parts, combine biases, zero h & c.
// g_W*[k][g*1024+n] = (k < 1024) ? w_h{g}[k][n] : w_i{g}[k-1024][n]
// ---------------------------------------------------------------------------
__global__ void prep_kernel(
    const float* __restrict__ w_ii, const float* __restrict__ w_hi,
    const float* __restrict__ w_if, const float* __restrict__ w_hf,
    const float* __restrict__ w_ig, const float* __restrict__ w_hg,
    const float* __restrict__ w_io, const float* __restrict__ w_ho,
    const float* __restrict__ b_ii, const float* __restrict__ b_hi,
    const float* __restrict__ b_if, const float* __restrict__ b_hf,
    const float* __restrict__ b_ig, const float* __restrict__ b_hg,
    const float* __restrict__ b_io, const float* __restrict__ b_ho,
    float* __restrict__ h, float* __restrict__ c)
{
    int idx = blockIdx.x * blockDim.x + threadIdx.x;
    if (idx < KTOT * NGC) {
        int k   = idx >> 12;          // / 4096
        int col = idx & (NGC - 1);
        int g   = col >> 10;
        int n   = col & (HID - 1);
        const float* src;
        if (k < HID) {
            const float* wh = (g == 0) ? w_hi : (g == 1) ? w_hf : (g == 2) ? w_hg : w_ho;
            src = wh + (size_t)k * HID + n;
        } else {
            const float* wi = (g == 0) ? w_ii : (g == 1) ? w_if : (g == 2) ? w_ig : w_io;
            src = wi + (size_t)(k - HID) * HID + n;
        }
        float w  = *src;
        float hi = to_tf32(w);
        g_Whi[idx] = hi;
        g_Wlo[idx] = to_tf32(w - hi);
    }
    if (idx < NGC) {
        int g = idx >> 10, n = idx & (HID - 1);
        const float* bi = (g == 0) ? b_ii : (g == 1) ? b_if : (g == 2) ? b_ig : b_io;
        const float* bh = (g == 0) ? b_hi : (g == 1) ? b_hf : (g == 2) ? b_hg : b_ho;
        g_bias[idx] = bi[n] + bh[n];
    }
    if (idx < HID * HID) {
        h[idx] = 0.0f;
        c[idx] = 0.0f;
    }
}

// ---------------------------------------------------------------------------
// Per-step GEMM (split-TF32): g_gates = [h | x_s] @ W + bias
// mma.sync m16n8k8 tf32; BM=128 BN=128 BK=16; 8 warps (2x4), warp tile 64x32.
// acc += Ahi*Bhi + Alo*Bhi + Ahi*Blo
// ---------------------------------------------------------------------------
__global__ __launch_bounds__(256) void lstm_gemm(
    const float* __restrict__ hbuf, const float* __restrict__ x, int s)
{
    __shared__ float As_hi[BM][BK + 4];
    __shared__ float As_lo[BM][BK + 4];
    __shared__ float Bs_hi[BK][BN + 4];
    __shared__ float Bs_lo[BK][BN + 4];

    const int tid  = threadIdx.x;
    const int lane = tid & 31;
    const int warp = tid >> 5;
    const int wm   = warp >> 2;   // 0..1
    const int wn   = warp & 3;    // 0..3
    const int bm   = blockIdx.y * BM;
    const int bn   = blockIdx.x * BN;

    float acc[4][4][4];
    #pragma unroll
    for (int a = 0; a < 4; ++a)
        #pragma unroll
        for (int b = 0; b < 4; ++b)
            #pragma unroll
            for (int v = 0; v < 4; ++v) acc[a][b][v] = 0.0f;

    const int ar  = tid >> 2;          // 0..63   (A tile rows)
    const int ac4 = (tid & 3) * 4;     // 0,4,8,12
    const int br  = tid >> 5;          // 0..7    (B tile rows)
    const int bc4 = lane * 4;          // 0..124

    for (int kt = 0; kt < KTOT / BK; ++kt) {
        const int  k0     = kt * BK;
        const bool from_h = (k0 < HID);

        #pragma unroll
        for (int rr = 0; rr < 2; ++rr) {
            const int row  = ar + rr * 64;
            const int grow = bm + row;
            const float* src = from_h
                ? hbuf + (size_t)grow * HID + (k0 + ac4)
                : x    + (size_t)grow * (SLEN * HID) + (size_t)s * HID + (k0 - HID + ac4);
            float4 v = *reinterpret_cast<const float4*>(src);
            float h0 = to_tf32(v.x), h1 = to_tf32(v.y), h2 = to_tf32(v.z), h3 = to_tf32(v.w);
            As_hi[row][ac4 + 0] = h0;  As_lo[row][ac4 + 0] = to_tf32(v.x - h0);
            As_hi[row][ac4 + 1] = h1;  As_lo[row][ac4 + 1] = to_tf32(v.y - h1);
            As_hi[row][ac4 + 2] = h2;  As_lo[row][ac4 + 2] = to_tf32(v.z - h2);
            As_hi[row][ac4 + 3] = h3;  As_lo[row][ac4 + 3] = to_tf32(v.w - h3);
        }
        #pragma unroll
        for (int rr = 0; rr < 2; ++rr) {
            const int row = br + rr * 8;
            const size_t off = (size_t)(k0 + row) * NGC + bn + bc4;
            float4 vh = *reinterpret_cast<const float4*>(&g_Whi[off]);
            float4 vl = *reinterpret_cast<const float4*>(&g_Wlo[off]);
            Bs_hi[row][bc4 + 0] = vh.x;  Bs_lo[row][bc4 + 0] = vl.x;
            Bs_hi[row][bc4 + 1] = vh.y;  Bs_lo[row][bc4 + 1] = vl.y;
            Bs_hi[row][bc4 + 2] = vh.z;  Bs_lo[row][bc4 + 2] = vl.z;
            Bs_hi[row][bc4 + 3] = vh.w;  Bs_lo[row][bc4 + 3] = vl.w;
        }
        __syncthreads();

        #pragma unroll
        for (int ks = 0; ks < BK; ks += 8) {
            uint32_t ah[4][4], al[4][4];
            #pragma unroll
            for (int mt = 0; mt < 4; ++mt) {
                const int r0 = wm * 64 + mt * 16 + (lane >> 2);
                const int kk = ks + (lane & 3);
                ah[mt][0] = __float_as_uint(As_hi[r0][kk]);
                ah[mt][1] = __float_as_uint(As_hi[r0 + 8][kk]);
                ah[mt][2] = __float_as_uint(As_hi[r0][kk + 4]);
                ah[mt][3] = __float_as_uint(As_hi[r0 + 8][kk + 4]);
                al[mt][0] = __float_as_uint(As_lo[r0][kk]);
                al[mt][1] = __float_as_uint(As_lo[r0 + 8][kk]);
                al[mt][2] = __float_as_uint(As_lo[r0][kk + 4]);
                al[mt][3] = __float_as_uint(As_lo[r0 + 8][kk + 4]);
            }
            uint32_t bh[4][2], bl[4][2];
            #pragma unroll
            for (int nt = 0; nt < 4; ++nt) {
                const int cc = wn * 32 + nt * 8 + (lane >> 2);
                const int kk = ks + (lane & 3);
                bh[nt][0] = __float_as_uint(Bs_hi[kk][cc]);
                bh[nt][1] = __float_as_uint(Bs_hi[kk + 4][cc]);
                bl[nt][0] = __float_as_uint(Bs_lo[kk][cc]);
                bl[nt][1] = __float_as_uint(Bs_lo[kk + 4][cc]);
            }
            #pragma unroll
            for (int mt = 0; mt < 4; ++mt) {
                #pragma unroll
                for (int nt = 0; nt < 4; ++nt) {
                    asm volatile(
                        "mma.sync.aligned.m16n8k8.row.col.f32.tf32.tf32.f32 "
                        "{%0,%1,%2,%3}, {%4,%5,%6,%7}, {%8,%9}, {%0,%1,%2,%3};\n"
                        : "+f"(acc[mt][nt][0]), "+f"(acc[mt][nt][1]),
                          "+f"(acc[mt][nt][2]), "+f"(acc[mt][nt][3])
                        : "r"(al[mt][0]), "r"(al[mt][1]), "r"(al[mt][2]), "r"(al[mt][3]),
                          "r"(bh[nt][0]), "r"(bh[nt][1]));
                    asm volatile(
                        "mma.sync.aligned.m16n8k8.row.col.f32.tf32.tf32.f32 "
                        "{%0,%1,%2,%3}, {%4,%5,%6,%7}, {%8,%9}, {%0,%1,%2,%3};\n"
                        : "+f"(acc[mt][nt][0]), "+f"(acc[mt][nt][1]),
                          "+f"(acc[mt][nt][2]), "+f"(acc[mt][nt][3])
                        : "r"(ah[mt][0]), "r"(ah[mt][1]), "r"(ah[mt][2]), "r"(ah[mt][3]),
                          "r"(bl[nt][0]), "r"(bl[nt][1]));
                    asm volatile(
                        "mma.sync.aligned.m16n8k8.row.col.f32.tf32.tf32.f32 "
                        "{%0,%1,%2,%3}, {%4,%5,%6,%7}, {%8,%9}, {%0,%1,%2,%3};\n"
                        : "+f"(acc[mt][nt][0]), "+f"(acc[mt][nt][1]),
                          "+f"(acc[mt][nt][2]), "+f"(acc[mt][nt][3])
                        : "r"(ah[mt][0]), "r"(ah[mt][1]), "r"(ah[mt][2]), "r"(ah[mt][3]),
                          "r"(bh[nt][0]), "r"(bh[nt][1]));
                }
            }
        }
        __syncthreads();
    }

    // Epilogue: add bias, store pre-activation gates
    #pragma unroll
    for (int mt = 0; mt < 4; ++mt) {
        const int row = bm + wm * 64 + mt * 16 + (lane >> 2);
        #pragma unroll
        for (int nt = 0; nt < 4; ++nt) {
            const int col = bn + wn * 32 + nt * 8 + (lane & 3) * 2;
            const float b0 = g_bias[col];
            const float b1 = g_bias[col + 1];
            g_gates[(size_t)row * NGC + col]           = acc[mt][nt][0] + b0;
            g_gates[(size_t)row * NGC + col + 1]       = acc[mt][nt][1] + b1;
            g_gates[(size_t)(row + 8) * NGC + col]     = acc[mt][nt][2] + b0;
            g_gates[(size_t)(row + 8) * NGC + col + 1] = acc[mt][nt][3] + b1;
        }
    }
}

// ---------------------------------------------------------------------------
// Cell update: i,f,o = sigmoid, g = tanh; c = f*c + i*g; h = o*tanh(c)
// ---------------------------------------------------------------------------
__global__ __launch_bounds__(256) void lstm_cell(float* __restrict__ h, float* __restrict__ c)
{
    const int idx = blockIdx.x * blockDim.x + threadIdx.x;   // 0 .. 1M-1
    const int b = idx >> 10;
    const int n = idx & (HID - 1);
    const float* gr = g_gates + (size_t)b * NGC;

    const float xi = gr[n];
    const float xf = gr[HID + n];
    const float xg = gr[2 * HID + n];
    const float xo = gr[3 * HID + n];

    const float ig = 1.0f / (1.0f + expf(-xi));
    const float fg = 1.0f / (1.0f + expf(-xf));
    const float gg = tanhf(xg);
    const float og = 1.0f / (1.0f + expf(-xo));

    const float cc = fg * c[idx] + ig * gg;
    c[idx] = cc;
    h[idx] = og * tanhf(cc);
}

// ---------------------------------------------------------------------------
extern "C" void kernel_launch(void* const* d_in, const int* in_sizes, int n_in,
                              void* d_out, int out_size)
{
    // Robust input parsing by element count (works for both signature-order
    // and grouped dict-order metadata):
    //   x: 1024*128*1024 elems;  weights: 1024*1024;  biases: 1024.
    // Relative order of weights is w_ii, w_hi, w_if, w_hf, w_ig, w_hg, w_io, w_ho
    // and biases b_ii, b_hi, b_if, b_hf, b_ig, b_hg, b_io, b_ho in either layout.
    const float* x = nullptr;
    const float* w[8] = {nullptr};
    const float* b[8] = {nullptr};
    int wi = 0, bi = 0;
    for (int i = 0; i < n_in; ++i) {
        const int sz = in_sizes[i];
        if (sz == HID * HID) {
            if (wi < 8) w[wi++] = (const float*)d_in[i];
        } else if (sz == HID) {
            if (bi < 8) b[bi++] = (const float*)d_in[i];
        } else {
            x = (const float*)d_in[i];   // the big (H,S,I) tensor
        }
    }

    float* h = (float*)d_out;                    // final h: first 1M floats
    float* c = h + (size_t)HID * HID;            // final c: next 1M floats

    {
        const int total = KTOT * NGC;            // 8,388,608
        prep_kernel<<<(total + 255) / 256, 256>>>(
            /*w_ii*/ w[0], /*w_hi*/ w[1], /*w_if*/ w[2], /*w_hf*/ w[3],
            /*w_ig*/ w[4], /*w_hg*/ w[5], /*w_io*/ w[6], /*w_ho*/ w[7],
            /*b_ii*/ b[0], /*b_hi*/ b[1], /*b_if*/ b[2], /*b_hf*/ b[3],
            /*b_ig*/ b[4], /*b_hg*/ b[5], /*b_io*/ b[6], /*b_ho*/ b[7],
            h, c);
    }

    dim3 grid(NGC / BN, HID / BM);               // 32 x 8 = 256 CTAs
    for (int s = 0; s < SLEN; ++s) {
        lstm_gemm<<<grid, 256>>>(h, x, s);
        lstm_cell<<<(HID * HID) / 256, 256>>>(h, c);
    }
}

// round 3
// speedup vs baseline: 3.3455x; 3.3455x over previous
#include <cuda_runtime.h>
#include <cuda_bf16.h>
#include <cstdint>
#include <cstddef>

// LSTM: batch B == H == 1024, S = 128, I = 1024.
// Per step: gates[1024 x 4096] = [h | x_s] (1024 x 2048) @ Wcat (2048 x 4096) + bias
// Split-BF16 (2-way split, 3 products) on m16n8k16 tensor cores ~ fp32 accuracy.
// GEMM is fully pre-converted: weights/x/h live as bf16 (hi,lo) pairs in global.

#define HID  1024
#define SLEN 128
#define NGC  4096            // 4 gates * HID (col order i, f, g, o)
#define KTOT 2048            // h (1024) | x_s (1024)

#define BM 128
#define BN 256
#define BK 32
#define NSLAB (KTOT / BK)    // 64

#define ASTR 40              // padded row stride (bf16 elems) = BK + 8 -> conflict-free
#define A_SPLIT_SZ (BM * ASTR)            // 5120 elems
#define B_SPLIT_SZ (BN * ASTR)            // 10240 elems
#define STAGE_SZ   (2 * A_SPLIT_SZ + 2 * B_SPLIT_SZ)   // 30720 elems
#define SMEM_BYTES (2 * STAGE_SZ * 2)                  // 122880 bytes (2 stages)

// ---- static device scratch (allocation forbidden) ----
__device__ __nv_bfloat16 g_W1[(size_t)NGC * KTOT];          // W^T hi  [col][k]  16 MB
__device__ __nv_bfloat16 g_W2[(size_t)NGC * KTOT];          // W^T lo            16 MB
__device__ __nv_bfloat16 g_X1[(size_t)HID * SLEN * HID];    // x hi [b][s][i]   256 MB
__device__ __nv_bfloat16 g_X2[(size_t)HID * SLEN * HID];    // x lo             256 MB
__device__ __nv_bfloat16 g_H1[(size_t)HID * HID];           // h hi [b][k]        2 MB
__device__ __nv_bfloat16 g_H2[(size_t)HID * HID];           // h lo               2 MB
__device__ float g_bias[NGC];
__device__ float g_gates[(size_t)HID * NGC];                // pre-activations   16 MB

__device__ __forceinline__ void cpa16(void* dst, const void* src) {
    uint32_t d = (uint32_t)__cvta_generic_to_shared(dst);
    asm volatile("cp.async.cg.shared.global [%0], [%1], 16;\n" :: "r"(d), "l"(src));
}
__device__ __forceinline__ uint32_t ld32(const __nv_bfloat16* p) {
    return *reinterpret_cast<const uint32_t*>(p);
}
__device__ __forceinline__ void mma16816(float* c, const uint32_t* a, const uint32_t* b) {
    asm volatile(
        "mma.sync.aligned.m16n8k16.row.col.f32.bf16.bf16.f32 "
        "{%0,%1,%2,%3}, {%4,%5,%6,%7}, {%8,%9}, {%0,%1,%2,%3};\n"
        : "+f"(c[0]), "+f"(c[1]), "+f"(c[2]), "+f"(c[3])
        : "r"(a[0]), "r"(a[1]), "r"(a[2]), "r"(a[3]), "r"(b[0]), "r"(b[1]));
}

// ---------------------------------------------------------------------------
// Prep 1: weights -> transposed bf16 splits. g_W*[col][k], col = g*1024+n.
// W[k][col] = (k < 1024) ? w_h{g}[k][n] : w_i{g}[k-1024][n]
// ---------------------------------------------------------------------------
__global__ void prep_weights(
    const float* __restrict__ w_ii, const float* __restrict__ w_hi,
    const float* __restrict__ w_if, const float* __restrict__ w_hf,
    const float* __restrict__ w_ig, const float* __restrict__ w_hg,
    const float* __restrict__ w_io, const float* __restrict__ w_ho)
{
    size_t idx = (size_t)blockIdx.x * blockDim.x + threadIdx.x;
    if (idx >= (size_t)NGC * KTOT) return;
    int col = (int)(idx >> 11);          // / 2048
    int k   = (int)(idx & (KTOT - 1));
    int g   = col >> 10;
    int n   = col & (HID - 1);
    float w;
    if (k < HID) {
        const float* wh = (g == 0) ? w_hi : (g == 1) ? w_hf : (g == 2) ? w_hg : w_ho;
        w = wh[(size_t)k * HID + n];
    } else {
        const float* wi = (g == 0) ? w_ii : (g == 1) ? w_if : (g == 2) ? w_ig : w_io;
        w = wi[(size_t)(k - HID) * HID + n];
    }
    __nv_bfloat16 hi = __float2bfloat16_rn(w);
    g_W1[idx] = hi;
    g_W2[idx] = __float2bfloat16_rn(w - __bfloat162float(hi));
}

// ---------------------------------------------------------------------------
// Prep 2: x -> bf16 splits (all timesteps, once per launch)
// ---------------------------------------------------------------------------
__global__ void prep_x(const float* __restrict__ x)
{
    size_t idx = (size_t)blockIdx.x * blockDim.x + threadIdx.x;
    if (idx >= (size_t)HID * SLEN * HID) return;
    float v = x[idx];
    __nv_bfloat16 hi = __float2bfloat16_rn(v);
    g_X1[idx] = hi;
    g_X2[idx] = __float2bfloat16_rn(v - __bfloat162float(hi));
}

// ---------------------------------------------------------------------------
// Prep 3: zero c and h-splits, combine biases
// ---------------------------------------------------------------------------
__global__ void prep_state(
    const float* __restrict__ b_ii, const float* __restrict__ b_hi,
    const float* __restrict__ b_if, const float* __restrict__ b_hf,
    const float* __restrict__ b_ig, const float* __restrict__ b_hg,
    const float* __restrict__ b_io, const float* __restrict__ b_ho,
    float* __restrict__ c)
{
    int idx = blockIdx.x * blockDim.x + threadIdx.x;
    if (idx < HID * HID) {
        c[idx]  = 0.0f;
        g_H1[idx] = __float2bfloat16_rn(0.0f);
        g_H2[idx] = __float2bfloat16_rn(0.0f);
    }
    if (idx < NGC) {
        int g = idx >> 10, n = idx & (HID - 1);
        const float* bi = (g == 0) ? b_ii : (g == 1) ? b_if : (g == 2) ? b_ig : b_io;
        const float* bh = (g == 0) ? b_hi : (g == 1) ? b_hf : (g == 2) ? b_hg : b_ho;
        g_bias[idx] = bi[n] + bh[n];
    }
}

// ---------------------------------------------------------------------------
// cp.async fill of one pipeline stage (one BK=32 k-slab)
// ---------------------------------------------------------------------------
__device__ __forceinline__ void fill_stage(
    __nv_bfloat16* sm, int stage, int kt, int s, int bm, int bn, int tid)
{
    __nv_bfloat16* base = sm + stage * STAGE_SZ;
    __nv_bfloat16* A1s = base;
    __nv_bfloat16* A2s = base + A_SPLIT_SZ;
    __nv_bfloat16* B1s = base + 2 * A_SPLIT_SZ;
    __nv_bfloat16* B2s = base + 2 * A_SPLIT_SZ + B_SPLIT_SZ;
    const int  k0     = kt * BK;
    const bool from_h = (k0 < HID);
    const __nv_bfloat16* s1 = from_h ? g_H1 : g_X1;
    const __nv_bfloat16* s2 = from_h ? g_H2 : g_X2;

    // A tile: 128 rows x 32 cols, 16B chunks: 512 per split, 2 per thread
    #pragma unroll
    for (int j = 0; j < 2; ++j) {
        int c   = tid + j * 256;
        int row = c >> 2, q = c & 3;
        int m   = bm + row;
        size_t off = from_h ? (size_t)m * HID + k0 + q * 8
                            : ((size_t)m * SLEN + s) * HID + (k0 - HID) + q * 8;
        cpa16(A1s + row * ASTR + q * 8, s1 + off);
        cpa16(A2s + row * ASTR + q * 8, s2 + off);
    }
    // B tile: 256 n-rows x 32 k, 1024 chunks per split, 4 per thread
    #pragma unroll
    for (int j = 0; j < 4; ++j) {
        int c = tid + j * 256;
        int n = c >> 2, q = c & 3;
        size_t off = (size_t)(bn + n) * KTOT + k0 + q * 8;
        cpa16(B1s + n * ASTR + q * 8, g_W1 + off);
        cpa16(B2s + n * ASTR + q * 8, g_W2 + off);
    }
}

// ---------------------------------------------------------------------------
// Per-step GEMM: g_gates = [h | x_s] @ W + bias  (split-bf16, 3 products)
// BM=128 BN=256 BK=32, 8 warps (2m x 4n), warp tile 64x64, double-buffered.
// ---------------------------------------------------------------------------
__global__ __launch_bounds__(256, 1) void lstm_gemm(int s)
{
    extern __shared__ __nv_bfloat16 sm[];
    const int tid  = threadIdx.x;
    const int lane = tid & 31;
    const int warp = tid >> 5;
    const int wm   = warp >> 2;   // 0..1
    const int wn   = warp & 3;    // 0..3
    const int bm   = blockIdx.y * BM;
    const int bn   = blockIdx.x * BN;

    float acc[4][8][4];
    #pragma unroll
    for (int a = 0; a < 4; ++a)
        #pragma unroll
        for (int b = 0; b < 8; ++b)
            #pragma unroll
            for (int v = 0; v < 4; ++v) acc[a][b][v] = 0.0f;

    fill_stage(sm, 0, 0, s, bm, bn, tid);
    asm volatile("cp.async.commit_group;\n");

    for (int kt = 0; kt < NSLAB; ++kt) {
        const int cur = kt & 1;
        if (kt + 1 < NSLAB)
            fill_stage(sm, (kt + 1) & 1, kt + 1, s, bm, bn, tid);
        asm volatile("cp.async.commit_group;\n");
        asm volatile("cp.async.wait_group 1;\n");
        __syncthreads();

        const __nv_bfloat16* base = sm + cur * STAGE_SZ;
        const __nv_bfloat16* A1s = base;
        const __nv_bfloat16* A2s = base + A_SPLIT_SZ;
        const __nv_bfloat16* B1s = base + 2 * A_SPLIT_SZ;
        const __nv_bfloat16* B2s = base + 2 * A_SPLIT_SZ + B_SPLIT_SZ;

        #pragma unroll
        for (int kk = 0; kk < 2; ++kk) {         // two k16 halves of the slab
            const int ko = kk * 16 + 2 * (lane & 3);
            uint32_t a1[4][4], a2[4][4];
            #pragma unroll
            for (int mt = 0; mt < 4; ++mt) {
                const int r = wm * 64 + mt * 16 + (lane >> 2);
                const __nv_bfloat16* p1 = A1s + r * ASTR + ko;
                const __nv_bfloat16* p2 = A2s + r * ASTR + ko;
                a1[mt][0] = ld32(p1);
                a1[mt][1] = ld32(p1 + 8 * ASTR);
                a1[mt][2] = ld32(p1 + 8);
                a1[mt][3] = ld32(p1 + 8 * ASTR + 8);
                a2[mt][0] = ld32(p2);
                a2[mt][1] = ld32(p2 + 8 * ASTR);
                a2[mt][2] = ld32(p2 + 8);
                a2[mt][3] = ld32(p2 + 8 * ASTR + 8);
            }
            uint32_t b1[8][2], b2[8][2];
            #pragma unroll
            for (int nt = 0; nt < 8; ++nt) {
                const int n = wn * 64 + nt * 8 + (lane >> 2);
                const __nv_bfloat16* p1 = B1s + n * ASTR + ko;
                const __nv_bfloat16* p2 = B2s + n * ASTR + ko;
                b1[nt][0] = ld32(p1);  b1[nt][1] = ld32(p1 + 8);
                b2[nt][0] = ld32(p2);  b2[nt][1] = ld32(p2 + 8);
            }
            #pragma unroll
            for (int mt = 0; mt < 4; ++mt) {
                #pragma unroll
                for (int nt = 0; nt < 8; ++nt) {
                    mma16816(acc[mt][nt], a1[mt], b1[nt]);   // A1*B1
                    mma16816(acc[mt][nt], a1[mt], b2[nt]);   // A1*B2
                    mma16816(acc[mt][nt], a2[mt], b1[nt]);   // A2*B1
                }
            }
        }
        __syncthreads();
    }

    // Epilogue: + bias, store pre-activation gates (float2 stores)
    #pragma unroll
    for (int mt = 0; mt < 4; ++mt) {
        const int row = bm + wm * 64 + mt * 16 + (lane >> 2);
        #pragma unroll
        for (int nt = 0; nt < 8; ++nt) {
            const int col = bn + wn * 64 + nt * 8 + 2 * (lane & 3);
            const float2 bb = *reinterpret_cast<const float2*>(&g_bias[col]);
            float2 v0 = { acc[mt][nt][0] + bb.x, acc[mt][nt][1] + bb.y };
            float2 v1 = { acc[mt][nt][2] + bb.x, acc[mt][nt][3] + bb.y };
            *reinterpret_cast<float2*>(&g_gates[(size_t)row * NGC + col])       = v0;
            *reinterpret_cast<float2*>(&g_gates[(size_t)(row + 8) * NGC + col]) = v1;
        }
    }
}

// ---------------------------------------------------------------------------
// Cell update (fused h-split): c = sig(f)*c + sig(i)*tanh(g); h = sig(o)*tanh(c)
// ---------------------------------------------------------------------------
__global__ __launch_bounds__(256) void lstm_cell(float* __restrict__ h, float* __restrict__ c)
{
    const int idx = blockIdx.x * blockDim.x + threadIdx.x;   // 0 .. 1M-1
    const int b = idx >> 10;
    const int n = idx & (HID - 1);
    const float* gr = g_gates + (size_t)b * NGC;

    const float xi = gr[n];
    const float xf = gr[HID + n];
    const float xg = gr[2 * HID + n];
    const float xo = gr[3 * HID + n];

    const float ig = 1.0f / (1.0f + expf(-xi));
    const float fg = 1.0f / (1.0f + expf(-xf));
    const float gg = tanhf(xg);
    const float og = 1.0f / (1.0f + expf(-xo));

    const float cc = fg * c[idx] + ig * gg;
    c[idx] = cc;
    const float hh = og * tanhf(cc);
    h[idx] = hh;

    __nv_bfloat16 h1 = __float2bfloat16_rn(hh);
    g_H1[idx] = h1;
    g_H2[idx] = __float2bfloat16_rn(hh - __bfloat162float(h1));
}

// ---------------------------------------------------------------------------
extern "C" void kernel_launch(void* const* d_in, const int* in_sizes, int n_in,
                              void* d_out, int out_size)
{
    // Parse by element count (robust to signature vs dict ordering; the
    // relative order of the 8 weights / 8 biases is identical in both).
    const float* x = nullptr;
    const float* w[8] = {nullptr};
    const float* b[8] = {nullptr};
    int wi = 0, bi = 0;
    for (int i = 0; i < n_in; ++i) {
        const int sz = in_sizes[i];
        if (sz == HID * HID)      { if (wi < 8) w[wi++] = (const float*)d_in[i]; }
        else if (sz == HID)       { if (bi < 8) b[bi++] = (const float*)d_in[i]; }
        else                      { x = (const float*)d_in[i]; }
    }

    float* h = (float*)d_out;                    // final h: first 1M floats
    float* c = h + (size_t)HID * HID;            // final c: next 1M floats

    cudaFuncSetAttribute(lstm_gemm, cudaFuncAttributeMaxDynamicSharedMemorySize, SMEM_BYTES);

    {
        const size_t total = (size_t)NGC * KTOT;            // 8.4M
        prep_weights<<<(unsigned)((total + 255) / 256), 256>>>(
            /*w_ii*/ w[0], /*w_hi*/ w[1], /*w_if*/ w[2], /*w_hf*/ w[3],
            /*w_ig*/ w[4], /*w_hg*/ w[5], /*w_io*/ w[6], /*w_ho*/ w[7]);
    }
    {
        const size_t total = (size_t)HID * SLEN * HID;      // 134M
        prep_x<<<(unsigned)((total + 255) / 256), 256>>>(x);
    }
    prep_state<<<(HID * HID) / 256, 256>>>(
        /*b_ii*/ b[0], /*b_hi*/ b[1], /*b_if*/ b[2], /*b_hf*/ b[3],
        /*b_ig*/ b[4], /*b_hg*/ b[5], /*b_io*/ b[6], /*b_ho*/ b[7], c);

    dim3 grid(NGC / BN, HID / BM);               // 16 x 8 = 128 CTAs, single wave
    for (int s = 0; s < SLEN; ++s) {
        lstm_gemm<<<grid, 256, SMEM_BYTES>>>(s);
        lstm_cell<<<(HID * HID) / 256, 256>>>(h, c);
    }
}

// round 5
// speedup vs baseline: 3.7993x; 1.1356x over previous
#include <cuda_runtime.h>
#include <cuda_bf16.h>
#include <cstdint>
#include <cstddef>

// LSTM: B == H == 1024, S = 128, I = 1024.
// Per step: gates[1024 x 4096] = [h | x_s] @ Wcat + bias, fused cell update.
// Split-BF16 (3 products) on mma.sync m16n8k16 (tcgen05 unavailable: harness
// builds for plain sm_103 PTX target). Gate columns interleaved: col' = 4n+g.

#define HID  1024
#define SLEN 128
#define NGC  4096
#define KTOT 2048

#define BM 128
#define BN 256
#define BK 32
#define NSLAB  (KTOT / BK)   // 64
#define NSTAGE 4

#define A_TILE_B 8192        // 128 rows * 32 bf16 * 2B
#define B_TILE_B 16384       // 256 rows * 32 bf16 * 2B
#define STAGE_B  (2 * A_TILE_B + 2 * B_TILE_B)   // 49152 (A1,A2,B1,B2)
#define SMEM_B   (NSTAGE * STAGE_B)              // 196608

#define GS 260               // gates smem row stride (floats)

// ---- static device scratch (allocation forbidden) ----
__device__ __nv_bfloat16 g_W1[(size_t)NGC * KTOT];        // W^T hi [col'][k]
__device__ __nv_bfloat16 g_W2[(size_t)NGC * KTOT];        // W^T lo
__device__ __nv_bfloat16 g_X1[(size_t)HID * SLEN * HID];  // x hi [b][s][i]
__device__ __nv_bfloat16 g_X2[(size_t)HID * SLEN * HID];  // x lo
__device__ __nv_bfloat16 g_Ha1[2][(size_t)HID * HID];     // h hi, double-buffered
__device__ __nv_bfloat16 g_Ha2[2][(size_t)HID * HID];     // h lo, double-buffered
__device__ float g_bias[NGC];                             // packed col' = 4n+g

// ---- helpers ----
__device__ __forceinline__ uint32_t smem_u32(const void* p) {
    uint32_t a;
    asm("{ .reg .u64 t; cvta.to.shared.u64 t, %1; cvt.u32.u64 %0, t; }" : "=r"(a) : "l"(p));
    return a;
}
__device__ __forceinline__ void cpa16(uint32_t dst, const void* src) {
    asm volatile("cp.async.cg.shared.global [%0], [%1], 16;\n" :: "r"(dst), "l"(src));
}
#define CP_COMMIT() asm volatile("cp.async.commit_group;" ::: "memory")

__device__ __forceinline__ void ldm_x4(uint32_t* r, uint32_t addr) {
    asm volatile("ldmatrix.sync.aligned.m8n8.x4.shared.b16 {%0,%1,%2,%3}, [%4];"
        : "=r"(r[0]), "=r"(r[1]), "=r"(r[2]), "=r"(r[3]) : "r"(addr));
}
__device__ __forceinline__ void mma16816(float* c, const uint32_t* a, const uint32_t* b) {
    asm volatile(
        "mma.sync.aligned.m16n8k16.row.col.f32.bf16.bf16.f32 "
        "{%0,%1,%2,%3}, {%4,%5,%6,%7}, {%8,%9}, {%0,%1,%2,%3};\n"
        : "+f"(c[0]), "+f"(c[1]), "+f"(c[2]), "+f"(c[3])
        : "r"(a[0]), "r"(a[1]), "r"(a[2]), "r"(a[3]), "r"(b[0]), "r"(b[1]));
}
// Swizzled smem byte offset for (row, 16B-chunk q) with 64B rows.
// Chunk index (row*4 + q') mod 8 is distinct across any 8 consecutive rows.
__device__ __forceinline__ uint32_t swq(int row, int q) {
    return (uint32_t)(row * 64 + ((q ^ ((row >> 1) & 3)) << 4));
}
__device__ __forceinline__ float sigm(float x) { return 1.0f / (1.0f + __expf(-x)); }
__device__ __forceinline__ float tanh_f(float x) { return 1.0f - 2.0f / (__expf(2.0f * x) + 1.0f); }

// ---------------------------------------------------------------------------
// Prep kernels
// ---------------------------------------------------------------------------
__global__ void prep_weights(
    const float* __restrict__ w_ii, const float* __restrict__ w_hi,
    const float* __restrict__ w_if, const float* __restrict__ w_hf,
    const float* __restrict__ w_ig, const float* __restrict__ w_hg,
    const float* __restrict__ w_io, const float* __restrict__ w_ho)
{
    size_t idx = (size_t)blockIdx.x * blockDim.x + threadIdx.x;
    if (idx >= (size_t)NGC * KTOT) return;
    int colp = (int)(idx >> 11);         // col' = 4n+g
    int k    = (int)(idx & (KTOT - 1));
    int n    = colp >> 2;
    int g    = colp & 3;
    float w;
    if (k < HID) {
        const float* wh = (g == 0) ? w_hi : (g == 1) ? w_hf : (g == 2) ? w_hg : w_ho;
        w = wh[(size_t)k * HID + n];
    } else {
        const float* wi = (g == 0) ? w_ii : (g == 1) ? w_if : (g == 2) ? w_ig : w_io;
        w = wi[(size_t)(k - HID) * HID + n];
    }
    __nv_bfloat16 hi = __float2bfloat16_rn(w);
    g_W1[idx] = hi;
    g_W2[idx] = __float2bfloat16_rn(w - __bfloat162float(hi));
}

__global__ void prep_x(const float* __restrict__ x)
{
    size_t idx = (size_t)blockIdx.x * blockDim.x + threadIdx.x;
    if (idx >= (size_t)HID * SLEN * HID) return;
    float v = x[idx];
    __nv_bfloat16 hi = __float2bfloat16_rn(v);
    g_X1[idx] = hi;
    g_X2[idx] = __float2bfloat16_rn(v - __bfloat162float(hi));
}

__global__ void prep_state(
    const float* __restrict__ b_ii, const float* __restrict__ b_hi,
    const float* __restrict__ b_if, const float* __restrict__ b_hf,
    const float* __restrict__ b_ig, const float* __restrict__ b_hg,
    const float* __restrict__ b_io, const float* __restrict__ b_ho,
    float* __restrict__ c)
{
    int idx = blockIdx.x * blockDim.x + threadIdx.x;
    if (idx < HID * HID) {
        c[idx] = 0.0f;
        g_Ha1[0][idx] = __float2bfloat16_rn(0.0f);
        g_Ha2[0][idx] = __float2bfloat16_rn(0.0f);
    }
    if (idx < NGC) {
        int n = idx >> 2, g = idx & 3;
        const float* bi = (g == 0) ? b_ii : (g == 1) ? b_if : (g == 2) ? b_ig : b_io;
        const float* bh = (g == 0) ? b_hi : (g == 1) ? b_hf : (g == 2) ? b_hg : b_ho;
        g_bias[idx] = bi[n] + bh[n];
    }
}

// ---------------------------------------------------------------------------
// cp.async fill of one BK=32 k-slab into one stage (swizzled 64B rows)
// ---------------------------------------------------------------------------
__device__ __forceinline__ void fill_stage(
    uint32_t sbase, int stage, int kt, int s, int rdbuf, int bm, int bn, int tid)
{
    const uint32_t st = sbase + stage * STAGE_B;
    const int k0 = kt * BK;
    const bool from_h = (k0 < HID);

    #pragma unroll
    for (int i = 0; i < 2; ++i) {               // A: 1024 16B chunks
        int cch   = tid + i * 512;
        int split = cch >> 9;
        int rem   = cch & 511;
        int row   = rem >> 2, q = rem & 3;
        const __nv_bfloat16* p;
        if (from_h) {
            size_t off = (size_t)(bm + row) * HID + k0 + q * 8;
            p = (split ? g_Ha2[rdbuf] : g_Ha1[rdbuf]) + off;
        } else {
            size_t off = ((size_t)(bm + row) * SLEN + s) * HID + (k0 - HID) + q * 8;
            p = (split ? g_X2 : g_X1) + off;
        }
        cpa16(st + split * A_TILE_B + swq(row, q), p);
    }
    #pragma unroll
    for (int i = 0; i < 4; ++i) {               // B: 2048 16B chunks
        int cch   = tid + i * 512;
        int split = cch >> 10;
        int rem   = cch & 1023;
        int row   = rem >> 2, q = rem & 3;
        size_t off = (size_t)(bn + row) * KTOT + k0 + q * 8;
        const __nv_bfloat16* p = (split ? g_W2 : g_W1) + off;
        cpa16(st + 2 * A_TILE_B + split * B_TILE_B + swq(row, q), p);
    }
}

// ---------------------------------------------------------------------------
// One LSTM step: split-bf16 GEMM (16 warps, ldmatrix, 4-stage) + fused cell
// ---------------------------------------------------------------------------
__global__ __launch_bounds__(512, 1) void lstm_step(
    int s, float* __restrict__ h_g, float* __restrict__ c_g)
{
    extern __shared__ __align__(128) char smem[];
    __shared__ __align__(16) float sbias[BN];

    const int tid  = threadIdx.x;
    const int lane = tid & 31;
    const int warp = tid >> 5;
    const int wm   = warp >> 2;      // 0..3 (m)
    const int wn   = warp & 3;       // 0..3 (n)
    const int bm   = blockIdx.y * BM;
    const int bn   = blockIdx.x * BN;
    const int rdbuf = s & 1;         // h buffer read parity
    const int wrbuf = rdbuf ^ 1;
    const uint32_t sbase = smem_u32(smem);

    if (tid < BN) sbias[tid] = g_bias[bn + tid];

    float acc[2][8][4];
    #pragma unroll
    for (int a = 0; a < 2; ++a)
        #pragma unroll
        for (int b = 0; b < 8; ++b)
            #pragma unroll
            for (int v = 0; v < 4; ++v) acc[a][b][v] = 0.0f;

    fill_stage(sbase, 0, 0, s, rdbuf, bm, bn, tid); CP_COMMIT();
    fill_stage(sbase, 1, 1, s, rdbuf, bm, bn, tid); CP_COMMIT();
    fill_stage(sbase, 2, 2, s, rdbuf, bm, bn, tid); CP_COMMIT();

    for (int kt = 0; kt < NSLAB; ++kt) {
        asm volatile("cp.async.wait_group 2;" ::: "memory");
        __syncthreads();
        if (kt + 3 < NSLAB)
            fill_stage(sbase, (kt + 3) & 3, kt + 3, s, rdbuf, bm, bn, tid);
        CP_COMMIT();

        const uint32_t stb = sbase + (kt & 3) * STAGE_B;
        #pragma unroll
        for (int kk = 0; kk < 2; ++kk) {        // two k16 halves of the slab
            uint32_t ra1[2][4], ra2[2][4];
            #pragma unroll
            for (int mt = 0; mt < 2; ++mt) {
                const int row = wm * 32 + mt * 16 + (lane & 15);
                const int q   = kk * 2 + (lane >> 4);
                const uint32_t ad = stb + swq(row, q);
                ldm_x4(ra1[mt], ad);
                ldm_x4(ra2[mt], ad + A_TILE_B);
            }
            #pragma unroll
            for (int p = 0; p < 4; ++p) {       // pairs of n8 tiles
                const int row = wn * 64 + p * 16 + (lane & 7) + ((lane >> 4) << 3);
                const int q   = kk * 2 + ((lane >> 3) & 1);
                const uint32_t bd = stb + 2 * A_TILE_B + swq(row, q);
                uint32_t rb1[4], rb2[4];
                ldm_x4(rb1, bd);
                ldm_x4(rb2, bd + B_TILE_B);
                #pragma unroll
                for (int mt = 0; mt < 2; ++mt) {
                    mma16816(acc[mt][2 * p],     ra1[mt], rb1);
                    mma16816(acc[mt][2 * p],     ra1[mt], rb2);
                    mma16816(acc[mt][2 * p],     ra2[mt], rb1);
                    mma16816(acc[mt][2 * p + 1], ra1[mt], rb1 + 2);
                    mma16816(acc[mt][2 * p + 1], ra1[mt], rb2 + 2);
                    mma16816(acc[mt][2 * p + 1], ra2[mt], rb1 + 2);
                }
            }
        }
    }
    asm volatile("cp.async.wait_group 0;" ::: "memory");
    __syncthreads();                 // stage smem now reusable for gates

    // ---- stage gates in smem ----
    float* gsm = (float*)smem;       // [128][GS]
    #pragma unroll
    for (int mt = 0; mt < 2; ++mt) {
        const int row = wm * 32 + mt * 16 + (lane >> 2);
        #pragma unroll
        for (int nt = 0; nt < 8; ++nt) {
            const int c0 = wn * 64 + nt * 8 + 2 * (lane & 3);
            *reinterpret_cast<float2*>(&gsm[row * GS + c0]) =
                make_float2(acc[mt][nt][0], acc[mt][nt][1]);
            *reinterpret_cast<float2*>(&gsm[(row + 8) * GS + c0]) =
                make_float2(acc[mt][nt][2], acc[mt][nt][3]);
        }
    }
    __syncthreads();

    // ---- fused cell update (coalesced, balanced across all 512 threads) ----
    const int n0g = bn >> 2;         // first hidden unit of this CTA (64 units)
    #pragma unroll 4
    for (int it = 0; it < 16; ++it) {
        const int row = it * 8 + (tid >> 6);
        const int n   = tid & 63;
        const float4 gv = *reinterpret_cast<const float4*>(&gsm[row * GS + 4 * n]);
        const float4 bv = *reinterpret_cast<const float4*>(&sbias[4 * n]);
        const float ig = sigm(gv.x + bv.x);
        const float fg = sigm(gv.y + bv.y);
        const float gg = tanh_f(gv.z + bv.z);
        const float og = sigm(gv.w + bv.w);
        const size_t gi = (size_t)(bm + row) * HID + n0g + n;
        const float cc = fg * c_g[gi] + ig * gg;
        c_g[gi] = cc;
        const float hh = og * tanh_f(cc);
        h_g[gi] = hh;
        const __nv_bfloat16 h1 = __float2bfloat16_rn(hh);
        g_Ha1[wrbuf][gi] = h1;
        g_Ha2[wrbuf][gi] = __float2bfloat16_rn(hh - __bfloat162float(h1));
    }
}

// ---------------------------------------------------------------------------
extern "C" void kernel_launch(void* const* d_in, const int* in_sizes, int n_in,
                              void* d_out, int out_size)
{
    const float* x = nullptr;
    const float* w[8] = {nullptr};
    const float* b[8] = {nullptr};
    int wi = 0, bi = 0;
    for (int i = 0; i < n_in; ++i) {
        const int sz = in_sizes[i];
        if (sz == HID * HID)      { if (wi < 8) w[wi++] = (const float*)d_in[i]; }
        else if (sz == HID)       { if (bi < 8) b[bi++] = (const float*)d_in[i]; }
        else                      { x = (const float*)d_in[i]; }
    }

    float* h = (float*)d_out;
    float* c = h + (size_t)HID * HID;

    cudaFuncSetAttribute(lstm_step, cudaFuncAttributeMaxDynamicSharedMemorySize, SMEM_B);

    {
        const size_t total = (size_t)NGC * KTOT;
        prep_weights<<<(unsigned)((total + 255) / 256), 256>>>(
            w[0], w[1], w[2], w[3], w[4], w[5], w[6], w[7]);
    }
    {
        const size_t total = (size_t)HID * SLEN * HID;
        prep_x<<<(unsigned)((total + 255) / 256), 256>>>(x);
    }
    prep_state<<<(HID * HID) / 256, 256>>>(
        b[0], b[1], b[2], b[3], b[4], b[5], b[6], b[7], c);

    dim3 grid(NGC / BN, HID / BM);    // 16 x 8 = 128 CTAs, single wave
    for (int s = 0; s < SLEN; ++s)
        lstm_step<<<grid, 512, SMEM_B>>>(s, h, c);
}

// round 6
// speedup vs baseline: 5.2350x; 1.3779x over previous
#include <cuda_runtime.h>
#include <cuda_fp16.h>
#include <cstdint>
#include <cstddef>

// LSTM: B == H == 1024, S = 128, I = 1024.
// Per step: gates[1024 x 4096] = [h | x_s] @ Wcat + bias, fused cell update.
// FP16 2-product scheme: A = fp16(A) (activations rounded once),
// W = W1 + W2 (fp16 split) -> gates ~= A*W1 + A*W2, missing term ~2^-12.
// mma.sync m16n8k16 f16 (tcgen05 unavailable: harness targets plain sm_103 PTX).
// Gate columns interleaved: col' = 4n+g  (g: 0=i,1=f,2=g,3=o).

#define HID  1024
#define SLEN 128
#define NGC  4096
#define KTOT 2048

#define BM 128
#define BN 256
#define BK 32
#define NSLAB  (KTOT / BK)   // 64
#define NSTAGE 4

#define A_TILE_B 8192        // 128 rows * 32 fp16 * 2B
#define B_TILE_B 16384       // 256 rows * 32 fp16 * 2B
#define STAGE_B  (A_TILE_B + 2 * B_TILE_B)       // 40960 (A, B1, B2)
#define SMEM_B   (NSTAGE * STAGE_B)              // 163840

#define GS 260               // gates smem row stride (floats)

// ---- static device scratch (allocation forbidden) ----
__device__ __half g_W1[(size_t)NGC * KTOT];        // W^T hi [col'][k]
__device__ __half g_W2[(size_t)NGC * KTOT];        // W^T lo (fp16 residual)
__device__ __half g_X[(size_t)HID * SLEN * HID];   // x fp16 [b][s][i]
__device__ __half g_Ha[2][(size_t)HID * HID];      // h fp16, double-buffered
__device__ float g_bias[NGC];                      // packed col' = 4n+g

// ---- helpers ----
__device__ __forceinline__ uint32_t smem_u32(const void* p) {
    uint32_t a;
    asm("{ .reg .u64 t; cvta.to.shared.u64 t, %1; cvt.u32.u64 %0, t; }" : "=r"(a) : "l"(p));
    return a;
}
__device__ __forceinline__ void cpa16(uint32_t dst, const void* src) {
    asm volatile("cp.async.cg.shared.global [%0], [%1], 16;\n" :: "r"(dst), "l"(src));
}
#define CP_COMMIT() asm volatile("cp.async.commit_group;" ::: "memory")

__device__ __forceinline__ void ldm_x4(uint32_t* r, uint32_t addr) {
    asm volatile("ldmatrix.sync.aligned.m8n8.x4.shared.b16 {%0,%1,%2,%3}, [%4];"
        : "=r"(r[0]), "=r"(r[1]), "=r"(r[2]), "=r"(r[3]) : "r"(addr));
}
__device__ __forceinline__ void mma16816(float* c, const uint32_t* a, const uint32_t* b) {
    asm volatile(
        "mma.sync.aligned.m16n8k16.row.col.f32.f16.f16.f32 "
        "{%0,%1,%2,%3}, {%4,%5,%6,%7}, {%8,%9}, {%0,%1,%2,%3};\n"
        : "+f"(c[0]), "+f"(c[1]), "+f"(c[2]), "+f"(c[3])
        : "r"(a[0]), "r"(a[1]), "r"(a[2]), "r"(a[3]), "r"(b[0]), "r"(b[1]));
}
// Swizzled smem byte offset for (row, 16B-chunk q), 64B rows: conflict-free
// for cp.async stores and 8-row ldmatrix phases.
__device__ __forceinline__ uint32_t swq(int row, int q) {
    return (uint32_t)(row * 64 + ((q ^ ((row >> 1) & 3)) << 4));
}
__device__ __forceinline__ float sigm(float x) { return 1.0f / (1.0f + __expf(-x)); }
__device__ __forceinline__ float tanh_f(float x) { return 1.0f - 2.0f / (__expf(2.0f * x) + 1.0f); }

// ---------------------------------------------------------------------------
// Prep kernels
// ---------------------------------------------------------------------------
__global__ void prep_weights(
    const float* __restrict__ w_ii, const float* __restrict__ w_hi,
    const float* __restrict__ w_if, const float* __restrict__ w_hf,
    const float* __restrict__ w_ig, const float* __restrict__ w_hg,
    const float* __restrict__ w_io, const float* __restrict__ w_ho)
{
    size_t idx = (size_t)blockIdx.x * blockDim.x + threadIdx.x;
    if (idx >= (size_t)NGC * KTOT) return;
    int colp = (int)(idx >> 11);         // col' = 4n+g
    int k    = (int)(idx & (KTOT - 1));
    int n    = colp >> 2;
    int g    = colp & 3;
    float w;
    if (k < HID) {
        const float* wh = (g == 0) ? w_hi : (g == 1) ? w_hf : (g == 2) ? w_hg : w_ho;
        w = wh[(size_t)k * HID + n];
    } else {
        const float* wi = (g == 0) ? w_ii : (g == 1) ? w_if : (g == 2) ? w_ig : w_io;
        w = wi[(size_t)(k - HID) * HID + n];
    }
    __half hi = __float2half_rn(w);
    g_W1[idx] = hi;
    g_W2[idx] = __float2half_rn(w - __half2float(hi));
}

__global__ void prep_x(const float* __restrict__ x)
{
    size_t idx = (size_t)blockIdx.x * blockDim.x + threadIdx.x;
    if (idx >= (size_t)HID * SLEN * HID) return;
    g_X[idx] = __float2half_rn(x[idx]);
}

__global__ void prep_state(
    const float* __restrict__ b_ii, const float* __restrict__ b_hi,
    const float* __restrict__ b_if, const float* __restrict__ b_hf,
    const float* __restrict__ b_ig, const float* __restrict__ b_hg,
    const float* __restrict__ b_io, const float* __restrict__ b_ho,
    float* __restrict__ c)
{
    int idx = blockIdx.x * blockDim.x + threadIdx.x;
    if (idx < HID * HID) {
        c[idx] = 0.0f;
        g_Ha[0][idx] = __float2half_rn(0.0f);
    }
    if (idx < NGC) {
        int n = idx >> 2, g = idx & 3;
        const float* bi = (g == 0) ? b_ii : (g == 1) ? b_if : (g == 2) ? b_ig : b_io;
        const float* bh = (g == 0) ? b_hi : (g == 1) ? b_hf : (g == 2) ? b_hg : b_ho;
        g_bias[idx] = bi[n] + bh[n];
    }
}

// ---------------------------------------------------------------------------
// cp.async fill of one BK=32 k-slab into one stage (swizzled 64B rows)
// ---------------------------------------------------------------------------
__device__ __forceinline__ void fill_stage(
    uint32_t sbase, int stage, int kt, int s, int rdbuf, int bm, int bn, int tid)
{
    const uint32_t st = sbase + stage * STAGE_B;
    const int k0 = kt * BK;
    const bool from_h = (k0 < HID);

    {   // A: 512 16B chunks, 1 per thread
        const int row = tid >> 2, q = tid & 3;
        const __half* p;
        if (from_h) {
            p = g_Ha[rdbuf] + (size_t)(bm + row) * HID + k0 + q * 8;
        } else {
            p = g_X + ((size_t)(bm + row) * SLEN + s) * HID + (k0 - HID) + q * 8;
        }
        cpa16(st + swq(row, q), p);
    }
    #pragma unroll
    for (int i = 0; i < 4; ++i) {               // B: 2048 16B chunks
        int cch   = tid + i * 512;
        int split = cch >> 10;
        int rem   = cch & 1023;
        int row   = rem >> 2, q = rem & 3;
        size_t off = (size_t)(bn + row) * KTOT + k0 + q * 8;
        const __half* p = (split ? g_W2 : g_W1) + off;
        cpa16(st + A_TILE_B + split * B_TILE_B + swq(row, q), p);
    }
}

// ---------------------------------------------------------------------------
// One LSTM step: fp16 2-product GEMM (16 warps, ldmatrix, 4-stage) + fused cell
// ---------------------------------------------------------------------------
__global__ __launch_bounds__(512, 1) void lstm_step(
    int s, float* __restrict__ h_g, float* __restrict__ c_g)
{
    extern __shared__ __align__(128) char smem[];
    __shared__ __align__(16) float sbias[BN];

    const int tid  = threadIdx.x;
    const int lane = tid & 31;
    const int warp = tid >> 5;
    const int wm   = warp >> 2;      // 0..3 (m)
    const int wn   = warp & 3;       // 0..3 (n)
    const int bm   = blockIdx.y * BM;
    const int bn   = blockIdx.x * BN;
    const int rdbuf = s & 1;         // h buffer read parity
    const int wrbuf = rdbuf ^ 1;
    const uint32_t sbase = smem_u32(smem);

    if (tid < BN) sbias[tid] = g_bias[bn + tid];

    float acc[2][8][4];
    #pragma unroll
    for (int a = 0; a < 2; ++a)
        #pragma unroll
        for (int b = 0; b < 8; ++b)
            #pragma unroll
            for (int v = 0; v < 4; ++v) acc[a][b][v] = 0.0f;

    fill_stage(sbase, 0, 0, s, rdbuf, bm, bn, tid); CP_COMMIT();
    fill_stage(sbase, 1, 1, s, rdbuf, bm, bn, tid); CP_COMMIT();
    fill_stage(sbase, 2, 2, s, rdbuf, bm, bn, tid); CP_COMMIT();

    for (int kt = 0; kt < NSLAB; ++kt) {
        asm volatile("cp.async.wait_group 2;" ::: "memory");
        __syncthreads();
        if (kt + 3 < NSLAB)
            fill_stage(sbase, (kt + 3) & 3, kt + 3, s, rdbuf, bm, bn, tid);
        CP_COMMIT();

        const uint32_t stb = sbase + (kt & 3) * STAGE_B;
        #pragma unroll
        for (int kk = 0; kk < 2; ++kk) {        // two k16 halves of the slab
            uint32_t ra[2][4];
            #pragma unroll
            for (int mt = 0; mt < 2; ++mt) {
                const int row = wm * 32 + mt * 16 + (lane & 15);
                const int q   = kk * 2 + (lane >> 4);
                ldm_x4(ra[mt], stb + swq(row, q));
            }
            #pragma unroll
            for (int p = 0; p < 4; ++p) {       // pairs of n8 tiles
                const int row = wn * 64 + p * 16 + (lane & 7) + ((lane >> 4) << 3);
                const int q   = kk * 2 + ((lane >> 3) & 1);
                const uint32_t bd = stb + A_TILE_B + swq(row, q);
                uint32_t rb1[4], rb2[4];
                ldm_x4(rb1, bd);
                ldm_x4(rb2, bd + B_TILE_B);
                #pragma unroll
                for (int mt = 0; mt < 2; ++mt) {
                    mma16816(acc[mt][2 * p],     ra[mt], rb1);
                    mma16816(acc[mt][2 * p],     ra[mt], rb2);
                    mma16816(acc[mt][2 * p + 1], ra[mt], rb1 + 2);
                    mma16816(acc[mt][2 * p + 1], ra[mt], rb2 + 2);
                }
            }
        }
    }
    asm volatile("cp.async.wait_group 0;" ::: "memory");
    __syncthreads();                 // stage smem now reusable for gates

    // ---- stage gates in smem ----
    float* gsm = (float*)smem;       // [128][GS]
    #pragma unroll
    for (int mt = 0; mt < 2; ++mt) {
        const int row = wm * 32 + mt * 16 + (lane >> 2);
        #pragma unroll
        for (int nt = 0; nt < 8; ++nt) {
            const int c0 = wn * 64 + nt * 8 + 2 * (lane & 3);
            *reinterpret_cast<float2*>(&gsm[row * GS + c0]) =
                make_float2(acc[mt][nt][0], acc[mt][nt][1]);
            *reinterpret_cast<float2*>(&gsm[(row + 8) * GS + c0]) =
                make_float2(acc[mt][nt][2], acc[mt][nt][3]);
        }
    }
    __syncthreads();

    // ---- fused cell update (coalesced across all 512 threads) ----
    const int n0g = bn >> 2;         // first hidden unit of this CTA (64 units)
    #pragma unroll 4
    for (int it = 0; it < 16; ++it) {
        const int row = it * 8 + (tid >> 6);
        const int n   = tid & 63;
        const float4 gv = *reinterpret_cast<const float4*>(&gsm[row * GS + 4 * n]);
        const float4 bv = *reinterpret_cast<const float4*>(&sbias[4 * n]);
        const float ig = sigm(gv.x + bv.x);
        const float fg = sigm(gv.y + bv.y);
        const float gg = tanh_f(gv.z + bv.z);
        const float og = sigm(gv.w + bv.w);
        const size_t gi = (size_t)(bm + row) * HID + n0g + n;
        const float cc = fg * c_g[gi] + ig * gg;
        c_g[gi] = cc;
        const float hh = og * tanh_f(cc);
        h_g[gi] = hh;
        g_Ha[wrbuf][gi] = __float2half_rn(hh);
    }
}

// ---------------------------------------------------------------------------
extern "C" void kernel_launch(void* const* d_in, const int* in_sizes, int n_in,
                              void* d_out, int out_size)
{
    const float* x = nullptr;
    const float* w[8] = {nullptr};
    const float* b[8] = {nullptr};
    int wi = 0, bi = 0;
    for (int i = 0; i < n_in; ++i) {
        const int sz = in_sizes[i];
        if (sz == HID * HID)      { if (wi < 8) w[wi++] = (const float*)d_in[i]; }
        else if (sz == HID)       { if (bi < 8) b[bi++] = (const float*)d_in[i]; }
        else                      { x = (const float*)d_in[i]; }
    }

    float* h = (float*)d_out;
    float* c = h + (size_t)HID * HID;

    cudaFuncSetAttribute(lstm_step, cudaFuncAttributeMaxDynamicSharedMemorySize, SMEM_B);

    {
        const size_t total = (size_t)NGC * KTOT;
        prep_weights<<<(unsigned)((total + 255) / 256), 256>>>(
            w[0], w[1], w[2], w[3], w[4], w[5], w[6], w[7]);
    }
    {
        const size_t total = (size_t)HID * SLEN * HID;
        prep_x<<<(unsigned)((total + 255) / 256), 256>>>(x);
    }
    prep_state<<<(HID * HID) / 256, 256>>>(
        b[0], b[1], b[2], b[3], b[4], b[5], b[6], b[7], c);

    dim3 grid(NGC / BN, HID / BM);    // 16 x 8 = 128 CTAs, single wave
    for (int s = 0; s < SLEN; ++s)
        lstm_step<<<grid, 512, SMEM_B>>>(s, h, c);
}

// round 7
// speedup vs baseline: 8.1334x; 1.5536x over previous
#include <cuda_runtime.h>
#include <cuda_fp16.h>
#include <cstdint>
#include <cstddef>

// LSTM: B == H == 1024, S = 128, I = 1024.
// Decomposition:
//   XP[b][s][col'] = x_s @ Wx + bias          (ONE parallel GEMM, all steps)
//   per step: gates = h @ Wh + XP[.,s,.]      (K=1024 fp16 GEMM, fused cell)
// All operands fp16 single-product (rel_err budget ~4e-4 < 1e-3).
// Gate columns interleaved: col' = 4n+g  (g: 0=i,1=f,2=g,3=o).

#define HID  1024
#define SLEN 128
#define NGC  4096
#define KH   1024            // K for both GEMMs
#define NSLAB (KH / 32)      // 32

#define BM 128
#define BN 256
#define BK 32
#define NSTAGE 4

#define A_TILE_B 8192        // 128 rows * 32 fp16 * 2B
#define B_TILE_B 16384       // 256 rows * 32 fp16 * 2B
#define STAGE_B  (A_TILE_B + B_TILE_B)     // 24576
#define GS 260               // gates smem row stride (floats)
#define GSM_B (128 * GS * 4) // 133120
#define SMEM_B GSM_B         // > 4*STAGE_B (98304)

// ---- static device scratch (allocation forbidden; each object < 2GB) ----
__device__ __half g_Wh[(size_t)NGC * KH];          // Wh^T fp16 [col'][k]   8 MB
__device__ __half g_Wx[(size_t)NGC * KH];          // Wx^T fp16 [col'][k]   8 MB
__device__ __half g_X[(size_t)HID * SLEN * HID];   // x fp16 [b][s][i]    256 MB
__device__ __half g_Ha[2][(size_t)HID * HID];      // h fp16, double-buffered
__device__ float g_bias[NGC];                      // packed col' = 4n+g
__device__ float g_XP0[(size_t)HID * 64 * NGC];    // XP s in [0,64)     1 GB
__device__ float g_XP1[(size_t)HID * 64 * NGC];    // XP s in [64,128)   1 GB

// ---- helpers ----
__device__ __forceinline__ uint32_t smem_u32(const void* p) {
    uint32_t a;
    asm("{ .reg .u64 t; cvta.to.shared.u64 t, %1; cvt.u32.u64 %0, t; }" : "=r"(a) : "l"(p));
    return a;
}
__device__ __forceinline__ void cpa16(uint32_t dst, const void* src) {
    asm volatile("cp.async.cg.shared.global [%0], [%1], 16;\n" :: "r"(dst), "l"(src));
}
#define CP_COMMIT() asm volatile("cp.async.commit_group;" ::: "memory")

__device__ __forceinline__ void ldm_x4(uint32_t* r, uint32_t addr) {
    asm volatile("ldmatrix.sync.aligned.m8n8.x4.shared.b16 {%0,%1,%2,%3}, [%4];"
        : "=r"(r[0]), "=r"(r[1]), "=r"(r[2]), "=r"(r[3]) : "r"(addr));
}
__device__ __forceinline__ void mma16816(float* c, const uint32_t* a, const uint32_t* b) {
    asm volatile(
        "mma.sync.aligned.m16n8k16.row.col.f32.f16.f16.f32 "
        "{%0,%1,%2,%3}, {%4,%5,%6,%7}, {%8,%9}, {%0,%1,%2,%3};\n"
        : "+f"(c[0]), "+f"(c[1]), "+f"(c[2]), "+f"(c[3])
        : "r"(a[0]), "r"(a[1]), "r"(a[2]), "r"(a[3]), "r"(b[0]), "r"(b[1]));
}
// Swizzled smem byte offset for (row, 16B chunk q), 64B rows.
__device__ __forceinline__ uint32_t swq(int row, int q) {
    return (uint32_t)(row * 64 + ((q ^ ((row >> 1) & 3)) << 4));
}
__device__ __forceinline__ float sigm(float x) { return 1.0f / (1.0f + __expf(-x)); }
__device__ __forceinline__ float tanh_f(float x) { return 1.0f - 2.0f / (__expf(2.0f * x) + 1.0f); }

// Shared mainloop compute for one BK=32 slab (1-product fp16)
__device__ __forceinline__ void slab_mma(
    uint32_t stb, int wm, int wn, int lane, float acc[2][8][4])
{
    #pragma unroll
    for (int kk = 0; kk < 2; ++kk) {
        uint32_t ra[2][4];
        #pragma unroll
        for (int mt = 0; mt < 2; ++mt) {
            const int row = wm * 32 + mt * 16 + (lane & 15);
            const int q   = kk * 2 + (lane >> 4);
            ldm_x4(ra[mt], stb + swq(row, q));
        }
        #pragma unroll
        for (int p = 0; p < 4; ++p) {
            const int row = wn * 64 + p * 16 + (lane & 7) + ((lane >> 4) << 3);
            const int q   = kk * 2 + ((lane >> 3) & 1);
            uint32_t rb[4];
            ldm_x4(rb, stb + A_TILE_B + swq(row, q));
            #pragma unroll
            for (int mt = 0; mt < 2; ++mt) {
                mma16816(acc[mt][2 * p],     ra[mt], rb);
                mma16816(acc[mt][2 * p + 1], ra[mt], rb + 2);
            }
        }
    }
}

// Stage accumulators into smem gates buffer
__device__ __forceinline__ void stage_gates(
    float* gsm, int wm, int wn, int lane, float acc[2][8][4])
{
    #pragma unroll
    for (int mt = 0; mt < 2; ++mt) {
        const int row = wm * 32 + mt * 16 + (lane >> 2);
        #pragma unroll
        for (int nt = 0; nt < 8; ++nt) {
            const int c0 = wn * 64 + nt * 8 + 2 * (lane & 3);
            *reinterpret_cast<float2*>(&gsm[row * GS + c0]) =
                make_float2(acc[mt][nt][0], acc[mt][nt][1]);
            *reinterpret_cast<float2*>(&gsm[(row + 8) * GS + c0]) =
                make_float2(acc[mt][nt][2], acc[mt][nt][3]);
        }
    }
}

// ---------------------------------------------------------------------------
// Prep kernels
// ---------------------------------------------------------------------------
__global__ void prep_weights(
    const float* __restrict__ w_ii, const float* __restrict__ w_hi,
    const float* __restrict__ w_if, const float* __restrict__ w_hf,
    const float* __restrict__ w_ig, const float* __restrict__ w_hg,
    const float* __restrict__ w_io, const float* __restrict__ w_ho)
{
    size_t idx = (size_t)blockIdx.x * blockDim.x + threadIdx.x;
    if (idx >= (size_t)NGC * KH) return;
    int colp = (int)(idx >> 10);         // col' = 4n+g
    int k    = (int)(idx & (KH - 1));
    int n    = colp >> 2;
    int g    = colp & 3;
    const float* wh = (g == 0) ? w_hi : (g == 1) ? w_hf : (g == 2) ? w_hg : w_ho;
    const float* wx = (g == 0) ? w_ii : (g == 1) ? w_if : (g == 2) ? w_ig : w_io;
    g_Wh[idx] = __float2half_rn(wh[(size_t)k * HID + n]);
    g_Wx[idx] = __float2half_rn(wx[(size_t)k * HID + n]);
}

__global__ void prep_x(const float* __restrict__ x)
{
    size_t idx = (size_t)blockIdx.x * blockDim.x + threadIdx.x;
    if (idx >= (size_t)HID * SLEN * HID) return;
    g_X[idx] = __float2half_rn(x[idx]);
}

__global__ void prep_state(
    const float* __restrict__ b_ii, const float* __restrict__ b_hi,
    const float* __restrict__ b_if, const float* __restrict__ b_hf,
    const float* __restrict__ b_ig, const float* __restrict__ b_hg,
    const float* __restrict__ b_io, const float* __restrict__ b_ho,
    float* __restrict__ c)
{
    int idx = blockIdx.x * blockDim.x + threadIdx.x;
    if (idx < HID * HID) {
        c[idx] = 0.0f;
        g_Ha[0][idx] = __float2half_rn(0.0f);
    }
    if (idx < NGC) {
        int n = idx >> 2, g = idx & 3;
        const float* bi = (g == 0) ? b_ii : (g == 1) ? b_if : (g == 2) ? b_ig : b_io;
        const float* bh = (g == 0) ? b_hi : (g == 1) ? b_hf : (g == 2) ? b_hg : b_ho;
        g_bias[idx] = bi[n] + bh[n];
    }
}

// ---------------------------------------------------------------------------
// Precompute GEMM: XP[row=b*128+s][col'] = x_row @ Wx + bias
// M=131072, N=4096, K=1024. grid (16, 1024), 512 threads.
// ---------------------------------------------------------------------------
__device__ __forceinline__ void fill_stage_pre(
    uint32_t sbase, int stage, int kt, size_t arow0, int bn, int tid)
{
    const uint32_t st = sbase + stage * STAGE_B;
    const int k0 = kt * BK;
    {   // A: 512 chunks
        const int row = tid >> 2, q = tid & 3;
        cpa16(st + swq(row, q), g_X + (arow0 + row) * KH + k0 + q * 8);
    }
    #pragma unroll
    for (int i = 0; i < 2; ++i) {   // B: 1024 chunks
        int cch = tid + i * 512;
        int row = cch >> 2, q = cch & 3;
        cpa16(st + A_TILE_B + swq(row, q), g_Wx + (size_t)(bn + row) * KH + k0 + q * 8);
    }
}

__global__ __launch_bounds__(512, 1) void xproj_gemm()
{
    extern __shared__ __align__(128) char smem[];
    __shared__ __align__(16) float sbias[BN];

    const int tid  = threadIdx.x;
    const int lane = tid & 31;
    const int warp = tid >> 5;
    const int wm   = warp >> 2;
    const int wn   = warp & 3;
    const int bn   = blockIdx.x * BN;
    const size_t arow0 = (size_t)blockIdx.y * BM;
    const uint32_t sbase = smem_u32(smem);

    if (tid < BN) sbias[tid] = g_bias[bn + tid];

    float acc[2][8][4];
    #pragma unroll
    for (int a = 0; a < 2; ++a)
        #pragma unroll
        for (int b = 0; b < 8; ++b)
            #pragma unroll
            for (int v = 0; v < 4; ++v) acc[a][b][v] = 0.0f;

    fill_stage_pre(sbase, 0, 0, arow0, bn, tid); CP_COMMIT();
    fill_stage_pre(sbase, 1, 1, arow0, bn, tid); CP_COMMIT();
    fill_stage_pre(sbase, 2, 2, arow0, bn, tid); CP_COMMIT();

    for (int kt = 0; kt < NSLAB; ++kt) {
        asm volatile("cp.async.wait_group 2;" ::: "memory");
        __syncthreads();
        if (kt + 3 < NSLAB)
            fill_stage_pre(sbase, (kt + 3) & 3, kt + 3, arow0, bn, tid);
        CP_COMMIT();
        slab_mma(sbase + (kt & 3) * STAGE_B, wm, wn, lane, acc);
    }
    asm volatile("cp.async.wait_group 0;" ::: "memory");
    __syncthreads();

    float* gsm = (float*)smem;
    stage_gates(gsm, wm, wn, lane, acc);
    __syncthreads();

    #pragma unroll 4
    for (int it = 0; it < 16; ++it) {
        const int row = it * 8 + (tid >> 6);
        const int n   = tid & 63;
        float4 gv = *reinterpret_cast<const float4*>(&gsm[row * GS + 4 * n]);
        const float4 bv = *reinterpret_cast<const float4*>(&sbias[4 * n]);
        gv.x += bv.x; gv.y += bv.y; gv.z += bv.z; gv.w += bv.w;
        const size_t rg = arow0 + row;
        const int bb = (int)(rg >> 7);
        const int ss = (int)(rg & 127);
        float* dst = (ss < 64 ? g_XP0 : g_XP1)
                   + ((size_t)bb * 64 + (ss & 63)) * NGC + bn + 4 * n;
        *reinterpret_cast<float4*>(dst) = gv;
    }
}

// ---------------------------------------------------------------------------
// Per-step: gates = h @ Wh + XP[.,s,.]; fused cell update.
// ---------------------------------------------------------------------------
__device__ __forceinline__ void fill_stage_h(
    uint32_t sbase, int stage, int kt, int rdbuf, int bm, int bn, int tid)
{
    const uint32_t st = sbase + stage * STAGE_B;
    const int k0 = kt * BK;
    {   // A: 512 chunks from h
        const int row = tid >> 2, q = tid & 3;
        cpa16(st + swq(row, q), g_Ha[rdbuf] + (size_t)(bm + row) * KH + k0 + q * 8);
    }
    #pragma unroll
    for (int i = 0; i < 2; ++i) {   // B: 1024 chunks from Wh
        int cch = tid + i * 512;
        int row = cch >> 2, q = cch & 3;
        cpa16(st + A_TILE_B + swq(row, q), g_Wh + (size_t)(bn + row) * KH + k0 + q * 8);
    }
}

__global__ __launch_bounds__(512, 1) void lstm_step(
    int s, float* __restrict__ h_g, float* __restrict__ c_g)
{
    extern __shared__ __align__(128) char smem[];

    const int tid  = threadIdx.x;
    const int lane = tid & 31;
    const int warp = tid >> 5;
    const int wm   = warp >> 2;
    const int wn   = warp & 3;
    const int bm   = blockIdx.y * BM;
    const int bn   = blockIdx.x * BN;
    const int rdbuf = s & 1;
    const int wrbuf = rdbuf ^ 1;
    const uint32_t sbase = smem_u32(smem);

    float acc[2][8][4];
    #pragma unroll
    for (int a = 0; a < 2; ++a)
        #pragma unroll
        for (int b = 0; b < 8; ++b)
            #pragma unroll
            for (int v = 0; v < 4; ++v) acc[a][b][v] = 0.0f;

    fill_stage_h(sbase, 0, 0, rdbuf, bm, bn, tid); CP_COMMIT();
    fill_stage_h(sbase, 1, 1, rdbuf, bm, bn, tid); CP_COMMIT();
    fill_stage_h(sbase, 2, 2, rdbuf, bm, bn, tid); CP_COMMIT();

    for (int kt = 0; kt < NSLAB; ++kt) {
        asm volatile("cp.async.wait_group 2;" ::: "memory");
        __syncthreads();
        if (kt + 3 < NSLAB)
            fill_stage_h(sbase, (kt + 3) & 3, kt + 3, rdbuf, bm, bn, tid);
        CP_COMMIT();
        slab_mma(sbase + (kt & 3) * STAGE_B, wm, wn, lane, acc);
    }
    asm volatile("cp.async.wait_group 0;" ::: "memory");
    __syncthreads();

    float* gsm = (float*)smem;
    stage_gates(gsm, wm, wn, lane, acc);
    __syncthreads();

    // ---- fused cell update with XP add (coalesced) ----
    const int n0g = bn >> 2;
    const float* xp = (s < 64 ? g_XP0 : g_XP1);
    const int ss = s & 63;
    #pragma unroll 4
    for (int it = 0; it < 16; ++it) {
        const int row = it * 8 + (tid >> 6);
        const int n   = tid & 63;
        const float4 gv = *reinterpret_cast<const float4*>(&gsm[row * GS + 4 * n]);
        const float4 xv = *reinterpret_cast<const float4*>(
            &xp[((size_t)(bm + row) * 64 + ss) * NGC + bn + 4 * n]);
        const float ig = sigm(gv.x + xv.x);
        const float fg = sigm(gv.y + xv.y);
        const float gg = tanh_f(gv.z + xv.z);
        const float og = sigm(gv.w + xv.w);
        const size_t gi = (size_t)(bm + row) * HID + n0g + n;
        const float cc = fg * c_g[gi] + ig * gg;
        c_g[gi] = cc;
        const float hh = og * tanh_f(cc);
        h_g[gi] = hh;
        g_Ha[wrbuf][gi] = __float2half_rn(hh);
    }
}

// ---------------------------------------------------------------------------
extern "C" void kernel_launch(void* const* d_in, const int* in_sizes, int n_in,
                              void* d_out, int out_size)
{
    const float* x = nullptr;
    const float* w[8] = {nullptr};
    const float* b[8] = {nullptr};
    int wi = 0, bi = 0;
    for (int i = 0; i < n_in; ++i) {
        const int sz = in_sizes[i];
        if (sz == HID * HID)      { if (wi < 8) w[wi++] = (const float*)d_in[i]; }
        else if (sz == HID)       { if (bi < 8) b[bi++] = (const float*)d_in[i]; }
        else                      { x = (const float*)d_in[i]; }
    }

    float* h = (float*)d_out;
    float* c = h + (size_t)HID * HID;

    cudaFuncSetAttribute(xproj_gemm, cudaFuncAttributeMaxDynamicSharedMemorySize, SMEM_B);
    cudaFuncSetAttribute(lstm_step,  cudaFuncAttributeMaxDynamicSharedMemorySize, SMEM_B);

    {
        const size_t total = (size_t)NGC * KH;
        prep_weights<<<(unsigned)((total + 255) / 256), 256>>>(
            w[0], w[1], w[2], w[3], w[4], w[5], w[6], w[7]);
    }
    {
        const size_t total = (size_t)HID * SLEN * HID;
        prep_x<<<(unsigned)((total + 255) / 256), 256>>>(x);
    }
    prep_state<<<(HID * HID) / 256, 256>>>(
        b[0], b[1], b[2], b[3], b[4], b[5], b[6], b[7], c);

    // Input projection for all 128 steps (one big GEMM)
    {
        dim3 grid(NGC / BN, (HID * SLEN) / BM);   // 16 x 1024
        xproj_gemm<<<grid, 512, SMEM_B>>>();
    }

    // Recurrence
    dim3 grid(NGC / BN, HID / BM);                // 16 x 8 = 128 CTAs
    for (int s = 0; s < SLEN; ++s)
        lstm_step<<<grid, 512, SMEM_B>>>(s, h, c);
}